// round 15
// baseline (speedup 1.0000x reference)
#include <cuda_runtime.h>
#include <cuda_fp16.h>
#include <cstdint>
#include <math.h>

// ---------------- problem shapes (fixed) ----------------
#define Tc   4096
#define Dc   2048
#define Hc   16
#define Lc   12
#define LHc  192
#define Mc   8192          // B*T
#define KKc  2048          // GEMM K
#define EPSV 1.1920929e-07f
#define INVSQRT2 0.70710678118654752440f

// ---------------- scratch (static device globals; zero-initialized) ----------
__device__ __half g_xh [(size_t)Mc * Dc];      // x fp16 hi
__device__ __half g_xl [(size_t)Mc * Dc];      // x fp16 lo (phi path only)
__device__ __half g_wth[(size_t)Dc * Dc];      // W_tok fp16
__device__ __half g_woh[(size_t)Dc * Dc];      // W_out fp16
__device__ __half g_wlh[(size_t)256 * Dc];     // W_lvl fp16 hi, padded 192->256 rows
__device__ __half g_wll[(size_t)256 * Dc];     // W_lvl fp16 lo
__device__ __half g_thh[(size_t)Mc * Dc];      // theta fp16 (pre-norm, then in-place butterfly)
__device__ float g_part  [(size_t)Mc * 32];    // per-(row, n-slab) sum-of-squares partials
__device__ float g_phi   [(size_t)Mc * 256];   // padded cols
__device__ float g_tscale[(size_t)Mc];
__device__ float2 g_sc   [(size_t)2 * Hc * Lc * Tc];

// ---------------- PTX helpers ----------------
__device__ __forceinline__ uint32_t smem_u32(const void* p) {
    uint32_t a;
    asm("{ .reg .u64 t; cvta.to.shared.u64 t, %1; cvt.u32.u64 %0, t; }" : "=r"(a) : "l"(p));
    return a;
}
__device__ __forceinline__ void cp_async16(uint32_t s, const void* g) {
    asm volatile("cp.async.cg.shared.global [%0], [%1], 16;" :: "r"(s), "l"(g));
}
#define CP_COMMIT() asm volatile("cp.async.commit_group;" ::: "memory")
#define CP_WAIT1()  asm volatile("cp.async.wait_group 1;" ::: "memory")
#define CP_WAIT0()  asm volatile("cp.async.wait_group 0;" ::: "memory")

#define LDSM4(d0,d1,d2,d3,a) \
    asm volatile("ldmatrix.sync.aligned.m8n8.x4.shared.b16 {%0,%1,%2,%3}, [%4];" \
        : "=r"(d0), "=r"(d1), "=r"(d2), "=r"(d3) : "r"(a))

#define MMA_F16(c, a0,a1,a2,a3, b0,b1) \
    asm volatile("mma.sync.aligned.m16n8k16.row.col.f32.f16.f16.f32 " \
        "{%0,%1,%2,%3}, {%4,%5,%6,%7}, {%8,%9}, {%0,%1,%2,%3};" \
        : "+f"((c)[0]), "+f"((c)[1]), "+f"((c)[2]), "+f"((c)[3]) \
        : "r"(a0), "r"(a1), "r"(a2), "r"(a3), "r"(b0), "r"(b1))

#define RB    80                        // smem row bytes: 32 halves (64B) + 16B pad
#define TILE  (128 * RB)                // 10240 B per operand tile
#define STG2  (2 * TILE)                // 20480 (single-pass stage: A,B)
#define STG4  (4 * TILE)                // 40960 (phi stage: Ah,Al,Bh,Bl)
#define NCH   (KKc / 32)                // 64 chunks

// ============== merged GEMM: theta (1-pass, fp16 out + ssq) + phi (3-pass) ===
__global__ __launch_bounds__(128, 2)
void f16_gemm_main(const __half* __restrict__ Ah, const __half* __restrict__ Al,
                   const __half* __restrict__ B, __half* __restrict__ Ct,
                   float* __restrict__ part,
                   const __half* __restrict__ Bh2, const __half* __restrict__ Bl2,
                   float* __restrict__ C2)
{
    extern __shared__ char smem[];
    const uint32_t sb = smem_u32(smem);
    const int tid  = threadIdx.x;
    const int wid  = tid >> 5;
    const int lane = tid & 31;
    const int m0 = blockIdx.y * 128;
    const int wm = (wid & 1) * 64;
    const int wn = (wid >> 1) * 64;
    const bool primary = (int)blockIdx.x < 16;

    const int g = lane >> 3, r = lane & 7;
    const int bTile = primary ? 1 : 2;      // B tile index within stage
    uint32_t aOff[4], bOff[4];
    #pragma unroll
    for (int mt = 0; mt < 4; mt++)
        aOff[mt] = (uint32_t)((wm + mt * 16 + (g & 1) * 8 + r) * RB + (g >> 1) * 16);
    #pragma unroll
    for (int nt2 = 0; nt2 < 4; nt2++)
        bOff[nt2] = (uint32_t)(bTile * TILE + (wn + nt2 * 16 + (g >> 1) * 8 + r) * RB + (g & 1) * 16);

    float acc[4][8][4];
    #pragma unroll
    for (int i = 0; i < 4; i++)
        #pragma unroll
        for (int j = 0; j < 8; j++)
            #pragma unroll
            for (int v = 0; v < 4; v++) acc[i][j][v] = 0.f;

    if (primary) {
        // ---------------- theta: 3-stage, 1 pass, 2 tiles ----------------
        const int n0 = blockIdx.x * 128;
        const __half* tp[2] = { Ah + (size_t)m0 * KKc, B + (size_t)n0 * KKc };

        auto load_stage = [&](int c, int st) {
            const uint32_t base = sb + st * STG2;
            #pragma unroll
            for (int t = 0; t < 2; t++) {
                const __half* src = tp[t] + c * 32;
                #pragma unroll
                for (int i = 0; i < 4; i++) {
                    const int idx = tid + i * 128;
                    const int row = idx >> 2;
                    const int ch  = idx & 3;
                    cp_async16(base + t * TILE + row * RB + ch * 16,
                               src + (size_t)row * KKc + ch * 8);
                }
            }
            CP_COMMIT();
        };

        load_stage(0, 0);
        load_stage(1, 1);

        for (int c = 0; c < NCH; c++) {
            if (c + 1 < NCH) CP_WAIT1(); else CP_WAIT0();
            __syncthreads();
            if (c + 2 < NCH) load_stage(c + 2, (c + 2) % 3);

            const uint32_t stb = sb + (c % 3) * STG2;
            #pragma unroll
            for (int ks = 0; ks < 2; ks++) {
                const uint32_t ko = ks * 32;
                uint32_t ah[4][4], bh[4][4];
                #pragma unroll
                for (int mt = 0; mt < 4; mt++)
                    LDSM4(ah[mt][0], ah[mt][1], ah[mt][2], ah[mt][3], stb + aOff[mt] + ko);
                #pragma unroll
                for (int nt2 = 0; nt2 < 4; nt2++)
                    LDSM4(bh[nt2][0], bh[nt2][1], bh[nt2][2], bh[nt2][3], stb + bOff[nt2] + ko);
                #pragma unroll
                for (int mt = 0; mt < 4; mt++)
                    #pragma unroll
                    for (int nt = 0; nt < 8; nt++) {
                        const uint32_t* bb = &bh[nt >> 1][(nt & 1) * 2];
                        MMA_F16(acc[mt][nt], ah[mt][0], ah[mt][1], ah[mt][2], ah[mt][3], bb[0], bb[1]);
                    }
            }
        }

        // ---- epilogue: fp16 theta + deterministic ssq partials ----
        const int slot = blockIdx.x * 2 + (wn >> 6);
        #pragma unroll
        for (int mt = 0; mt < 4; mt++) {
            const int m = m0 + wm + mt * 16 + (lane >> 2);
            float ss0 = 0.f, ss1 = 0.f;
            #pragma unroll
            for (int nt = 0; nt < 8; nt++) {
                const int n = n0 + wn + nt * 8 + (lane & 3) * 2;
                const float a0 = acc[mt][nt][0], a1 = acc[mt][nt][1];
                const float a2 = acc[mt][nt][2], a3 = acc[mt][nt][3];
                *(__half2*)(Ct + (size_t)m * Dc + n)       = __floats2half2_rn(a0, a1);
                *(__half2*)(Ct + (size_t)(m + 8) * Dc + n) = __floats2half2_rn(a2, a3);
                ss0 = fmaf(a0, a0, fmaf(a1, a1, ss0));
                ss1 = fmaf(a2, a2, fmaf(a3, a3, ss1));
            }
            ss0 += __shfl_xor_sync(0xffffffffu, ss0, 1);
            ss0 += __shfl_xor_sync(0xffffffffu, ss0, 2);
            ss1 += __shfl_xor_sync(0xffffffffu, ss1, 1);
            ss1 += __shfl_xor_sync(0xffffffffu, ss1, 2);
            if ((lane & 3) == 0) {
                part[(size_t)m * 32 + slot]       = ss0;
                part[(size_t)(m + 8) * 32 + slot] = ss1;
            }
        }
    } else {
        // ---------------- phi: 2-stage, 3 passes, 4 tiles ----------------
        const int n0 = ((int)blockIdx.x - 16) * 128;
        const bool active = (n0 + wn) < LHc;       // skip pure-padding warp columns
        const __half* tp[4] = { Ah + (size_t)m0 * KKc, Al + (size_t)m0 * KKc,
                                Bh2 + (size_t)n0 * KKc, Bl2 + (size_t)n0 * KKc };

        auto load_stage4 = [&](int c, int st) {
            const uint32_t base = sb + st * STG4;
            #pragma unroll
            for (int i = 0; i < 16; i++) {
                const int idx = tid + i * 128;       // 0..2047
                const int t   = idx >> 9;
                const int rem = idx & 511;
                const int row = rem >> 2;
                const int ch  = rem & 3;
                cp_async16(base + t * TILE + row * RB + ch * 16,
                           tp[t] + (size_t)row * KKc + c * 32 + ch * 8);
            }
            CP_COMMIT();
        };

        load_stage4(0, 0);

        for (int c = 0; c < NCH; c++) {
            if (c + 1 < NCH) { load_stage4(c + 1, (c + 1) & 1); CP_WAIT1(); }
            else             { CP_WAIT0(); }
            __syncthreads();

            const uint32_t stb = sb + (c & 1) * STG4;
            if (active) {
                #pragma unroll
                for (int ks = 0; ks < 2; ks++) {
                    const uint32_t ko = ks * 32;
                    uint32_t ah[4][4], bh[4][4], xx[4][4];

                    #pragma unroll
                    for (int mt = 0; mt < 4; mt++)
                        LDSM4(ah[mt][0], ah[mt][1], ah[mt][2], ah[mt][3], stb + aOff[mt] + ko);
                    #pragma unroll
                    for (int nt2 = 0; nt2 < 4; nt2++)
                        LDSM4(bh[nt2][0], bh[nt2][1], bh[nt2][2], bh[nt2][3], stb + bOff[nt2] + ko);
                    #pragma unroll
                    for (int mt = 0; mt < 4; mt++)
                        #pragma unroll
                        for (int nt = 0; nt < 8; nt++) {
                            const uint32_t* bb = &bh[nt >> 1][(nt & 1) * 2];
                            MMA_F16(acc[mt][nt], ah[mt][0], ah[mt][1], ah[mt][2], ah[mt][3], bb[0], bb[1]);
                        }

                    #pragma unroll
                    for (int mt = 0; mt < 4; mt++)
                        LDSM4(xx[mt][0], xx[mt][1], xx[mt][2], xx[mt][3], stb + TILE + aOff[mt] + ko);
                    #pragma unroll
                    for (int mt = 0; mt < 4; mt++)
                        #pragma unroll
                        for (int nt = 0; nt < 8; nt++) {
                            const uint32_t* bb = &bh[nt >> 1][(nt & 1) * 2];
                            MMA_F16(acc[mt][nt], xx[mt][0], xx[mt][1], xx[mt][2], xx[mt][3], bb[0], bb[1]);
                        }

                    #pragma unroll
                    for (int nt2 = 0; nt2 < 4; nt2++)
                        LDSM4(xx[nt2][0], xx[nt2][1], xx[nt2][2], xx[nt2][3], stb + TILE + bOff[nt2] + ko);
                    #pragma unroll
                    for (int mt = 0; mt < 4; mt++)
                        #pragma unroll
                        for (int nt = 0; nt < 8; nt++) {
                            const uint32_t* bb = &xx[nt >> 1][(nt & 1) * 2];
                            MMA_F16(acc[mt][nt], ah[mt][0], ah[mt][1], ah[mt][2], ah[mt][3], bb[0], bb[1]);
                        }
                }
            }
            __syncthreads();
        }

        if (active) {
            #pragma unroll
            for (int mt = 0; mt < 4; mt++) {
                const int m = m0 + wm + mt * 16 + (lane >> 2);
                #pragma unroll
                for (int nt = 0; nt < 8; nt++) {
                    const int n = n0 + wn + nt * 8 + (lane & 3) * 2;
                    *(float2*)(C2 + (size_t)m * 256 + n)       = make_float2(acc[mt][nt][0], acc[mt][nt][1]);
                    *(float2*)(C2 + (size_t)(m + 8) * 256 + n) = make_float2(acc[mt][nt][2], acc[mt][nt][3]);
                }
            }
        }
    }
}

// ================= GEMM3: single-pass fp16 ==================
__global__ __launch_bounds__(128, 2)
void f16_gemm1(const __half* __restrict__ A, const __half* __restrict__ B,
               float* __restrict__ C)
{
    extern __shared__ char smem[];
    const uint32_t sb = smem_u32(smem);
    const int tid  = threadIdx.x;
    const int wid  = tid >> 5;
    const int lane = tid & 31;
    const int m0 = blockIdx.y * 128;
    const int n0 = blockIdx.x * 128;
    const int wm = (wid & 1) * 64;
    const int wn = (wid >> 1) * 64;

    const int g = lane >> 3, r = lane & 7;
    uint32_t aOff[4], bOff[4];
    #pragma unroll
    for (int mt = 0; mt < 4; mt++)
        aOff[mt] = (uint32_t)((wm + mt * 16 + (g & 1) * 8 + r) * RB + (g >> 1) * 16);
    #pragma unroll
    for (int nt2 = 0; nt2 < 4; nt2++)
        bOff[nt2] = (uint32_t)(TILE + (wn + nt2 * 16 + (g >> 1) * 8 + r) * RB + (g & 1) * 16);

    float acc[4][8][4];
    #pragma unroll
    for (int i = 0; i < 4; i++)
        #pragma unroll
        for (int j = 0; j < 8; j++)
            #pragma unroll
            for (int v = 0; v < 4; v++) acc[i][j][v] = 0.f;

    const __half* tp[2] = { A + (size_t)m0 * KKc, B + (size_t)n0 * KKc };

    auto load_stage = [&](int c, int st) {
        const uint32_t base = sb + st * STG2;
        #pragma unroll
        for (int t = 0; t < 2; t++) {
            const __half* src = tp[t] + c * 32;
            #pragma unroll
            for (int i = 0; i < 4; i++) {
                const int idx = tid + i * 128;
                const int row = idx >> 2;
                const int ch  = idx & 3;
                cp_async16(base + t * TILE + row * RB + ch * 16,
                           src + (size_t)row * KKc + ch * 8);
            }
        }
        CP_COMMIT();
    };

    load_stage(0, 0);
    load_stage(1, 1);

    for (int c = 0; c < NCH; c++) {
        if (c + 1 < NCH) CP_WAIT1(); else CP_WAIT0();
        __syncthreads();
        if (c + 2 < NCH) load_stage(c + 2, (c + 2) % 3);

        const uint32_t stb = sb + (c % 3) * STG2;
        #pragma unroll
        for (int ks = 0; ks < 2; ks++) {
            const uint32_t ko = ks * 32;
            uint32_t ah[4][4], bh[4][4];
            #pragma unroll
            for (int mt = 0; mt < 4; mt++)
                LDSM4(ah[mt][0], ah[mt][1], ah[mt][2], ah[mt][3], stb + aOff[mt] + ko);
            #pragma unroll
            for (int nt2 = 0; nt2 < 4; nt2++)
                LDSM4(bh[nt2][0], bh[nt2][1], bh[nt2][2], bh[nt2][3], stb + bOff[nt2] + ko);
            #pragma unroll
            for (int mt = 0; mt < 4; mt++)
                #pragma unroll
                for (int nt = 0; nt < 8; nt++) {
                    const uint32_t* bb = &bh[nt >> 1][(nt & 1) * 2];
                    MMA_F16(acc[mt][nt], ah[mt][0], ah[mt][1], ah[mt][2], ah[mt][3], bb[0], bb[1]);
                }
        }
    }

    #pragma unroll
    for (int mt = 0; mt < 4; mt++) {
        const int m = m0 + wm + mt * 16 + (lane >> 2);
        #pragma unroll
        for (int nt = 0; nt < 8; nt++) {
            const int n = n0 + wn + nt * 8 + (lane & 3) * 2;
            *(float2*)(C + (size_t)m * Dc + n)       = make_float2(acc[mt][nt][0], acc[mt][nt][1]);
            *(float2*)(C + (size_t)(m + 8) * Dc + n) = make_float2(acc[mt][nt][2], acc[mt][nt][3]);
        }
    }
}

// ---------------- fused operand conversions (one kernel) ----------------
__device__ __forceinline__ void split4(float4 v, uint2* H, uint2* L, int i) {
    __half h0 = __float2half_rn(v.x), h1 = __float2half_rn(v.y);
    __half h2 = __float2half_rn(v.z), h3 = __float2half_rn(v.w);
    __half l0 = __float2half_rn(v.x - __half2float(h0));
    __half l1 = __float2half_rn(v.y - __half2float(h1));
    __half l2 = __float2half_rn(v.z - __half2float(h2));
    __half l3 = __float2half_rn(v.w - __half2float(h3));
    __half2 ha = {h0, h1}, hb = {h2, h3}, la = {l0, l1}, lb = {l2, l3};
    H[i] = make_uint2(*(uint32_t*)&ha, *(uint32_t*)&hb);
    L[i] = make_uint2(*(uint32_t*)&la, *(uint32_t*)&lb);
}
__device__ __forceinline__ void cvt4(float4 v, uint2* H, int i) {
    __half2 a = __floats2half2_rn(v.x, v.y);
    __half2 b = __floats2half2_rn(v.z, v.w);
    H[i] = make_uint2(*(uint32_t*)&a, *(uint32_t*)&b);
}

#define N_X  (Mc * Dc / 4)
#define N_W  (Dc * Dc / 4)
#define N_L  (LHc * Dc / 4)
#define N_ALL (N_X + 2 * N_W + N_L)

__global__ void cvt_all(const float4* __restrict__ x, const float4* __restrict__ wt,
                        const float4* __restrict__ wo, const float4* __restrict__ wl,
                        uint2* __restrict__ xh, uint2* __restrict__ xl,
                        uint2* __restrict__ wth, uint2* __restrict__ woh,
                        uint2* __restrict__ wlh, uint2* __restrict__ wll)
{
    int i = blockIdx.x * blockDim.x + threadIdx.x;
    if (i < N_X) {
        split4(x[i], xh, xl, i);
    } else if (i < N_X + N_W) {
        int j = i - N_X;
        cvt4(wt[j], wth, j);
    } else if (i < N_X + 2 * N_W) {
        int j = i - N_X - N_W;
        cvt4(wo[j], woh, j);
    } else if (i < N_ALL) {
        int j = i - N_X - 2 * N_W;
        split4(wl[j], wlh, wll, j);
    }
}

// ------- fused: theta-scale finish + RMSNorm(phi) + sincos transpose -------
__global__ __launch_bounds__(192)
void phi_rms_sincos(const float* __restrict__ phi, const float* __restrict__ part,
                    float* __restrict__ tscale, float2* __restrict__ sc)
{
    const int row = blockIdx.x;            // b*4096 + t
    const int t   = row & (Tc - 1);
    const int b   = row >> 12;
    const int j   = threadIdx.x;           // 0..191

    // warp 0: finish theta rms scale from 32 slab partials
    if (j < 32) {
        float ss = part[(size_t)row * 32 + j];
        #pragma unroll
        for (int o = 16; o > 0; o >>= 1) ss += __shfl_xor_sync(0xffffffffu, ss, o);
        if (j == 0) tscale[row] = rsqrtf(ss / (float)Dc + EPSV);
    }

    const float v = phi[(size_t)row * 256 + j];
    float ss = v * v;
    #pragma unroll
    for (int o = 16; o > 0; o >>= 1) ss += __shfl_xor_sync(0xffffffffu, ss, o);
    __shared__ float red[6];
    const int warp = j >> 5, lane = j & 31;
    if (lane == 0) red[warp] = ss;
    __syncthreads();
    float tot = red[0] + red[1] + red[2] + red[3] + red[4] + red[5];
    const float rs = rsqrtf(tot / (float)LHc + EPSV);

    float s, c;
    sincosf(v * rs, &s, &c);
    const int l = j >> 4, h = j & 15;
    sc[((size_t)(b * Hc + h) * Lc + l) * Tc + t] = make_float2(c * INVSQRT2, s * INVSQRT2);
}

// ---------------- fused 12-level butterfly (fp16 in-place, 8-float slice) ----
// R13 structure (known-good) + software prefetch: level l+1's sc coefficients
// are loaded right after level l's FMAs (old w registers dead -> reuse), hiding
// the per-level L2 latency behind the STS/barrier phase.
#define BSTR 12
__global__ __launch_bounds__(512, 1)
void butterfly_fused(__half* __restrict__ Th, const float* __restrict__ tscale,
                     const float2* __restrict__ sc)
{
    extern __shared__ float th[];   // [4096][BSTR]
    const int ds  = blockIdx.x;     // 0..15
    const int h   = blockIdx.y;     // 0..15
    const int b   = blockIdx.z;     // 0..1
    const int tid = threadIdx.x;
    const int cb  = h * 128 + ds * 8;
    const size_t rowbase = (size_t)b * Tc;

    float cur[8][8];

    #pragma unroll
    for (int k = 0; k < 8; k++) {
        const int t = tid + k * 512;
        const float scl = tscale[rowbase + t];
        uint4 raw = *(const uint4*)(Th + (rowbase + t) * Dc + cb);
        const __half2* hp = (const __half2*)&raw;
        #pragma unroll
        for (int p = 0; p < 4; p++) {
            float2 f = __half22float2(hp[p]);
            cur[k][p * 2]     = f.x * scl;
            cur[k][p * 2 + 1] = f.y * scl;
        }
        float* s = &th[t * BSTR];
        *(float4*)s       = make_float4(cur[k][0], cur[k][1], cur[k][2], cur[k][3]);
        *(float4*)(s + 4) = make_float4(cur[k][4], cur[k][5], cur[k][6], cur[k][7]);
    }

    const float2* scb = sc + (size_t)(b * Hc + h) * Lc * Tc;
    float2 w[8];
    #pragma unroll
    for (int k = 0; k < 8; k++) w[k] = scb[tid + k * 512];   // level 0 coeffs
    __syncthreads();

    #pragma unroll
    for (int l = 0; l < Lc; l++) {
        const int step = 1 << l;
        #pragma unroll
        for (int k = 0; k < 8; k++) {
            const int t = tid + k * 512;
            float4 p0 = make_float4(0.f, 0.f, 0.f, 0.f);
            float4 p1 = p0;
            if (t >= step) {
                const float* ps = &th[(t - step) * BSTR];
                p0 = *(const float4*)ps;
                p1 = *(const float4*)(ps + 4);
            }
            cur[k][0] = fmaf(w[k].x, cur[k][0], w[k].y * p0.x);
            cur[k][1] = fmaf(w[k].x, cur[k][1], w[k].y * p0.y);
            cur[k][2] = fmaf(w[k].x, cur[k][2], w[k].y * p0.z);
            cur[k][3] = fmaf(w[k].x, cur[k][3], w[k].y * p0.w);
            cur[k][4] = fmaf(w[k].x, cur[k][4], w[k].y * p1.x);
            cur[k][5] = fmaf(w[k].x, cur[k][5], w[k].y * p1.y);
            cur[k][6] = fmaf(w[k].x, cur[k][6], w[k].y * p1.z);
            cur[k][7] = fmaf(w[k].x, cur[k][7], w[k].y * p1.w);
        }
        // prefetch next level's coeffs (w now dead; regs reused)
        if (l + 1 < Lc) {
            #pragma unroll
            for (int k = 0; k < 8; k++) w[k] = scb[(l + 1) * Tc + tid + k * 512];
        }
        __syncthreads();                 // all reads of old level done
        if (l < Lc - 1) {
            #pragma unroll
            for (int k = 0; k < 8; k++) {
                float* s = &th[(tid + k * 512) * BSTR];
                *(float4*)s       = make_float4(cur[k][0], cur[k][1], cur[k][2], cur[k][3]);
                *(float4*)(s + 4) = make_float4(cur[k][4], cur[k][5], cur[k][6], cur[k][7]);
            }
            __syncthreads();             // new level visible
        }
    }

    #pragma unroll
    for (int k = 0; k < 8; k++) {
        const int t = tid + k * 512;
        __half2 h0 = __floats2half2_rn(cur[k][0], cur[k][1]);
        __half2 h1 = __floats2half2_rn(cur[k][2], cur[k][3]);
        __half2 h2 = __floats2half2_rn(cur[k][4], cur[k][5]);
        __half2 h3 = __floats2half2_rn(cur[k][6], cur[k][7]);
        uint4 o;
        o.x = *(uint32_t*)&h0; o.y = *(uint32_t*)&h1;
        o.z = *(uint32_t*)&h2; o.w = *(uint32_t*)&h3;
        *(uint4*)(Th + (rowbase + t) * Dc + cb) = o;
    }
}

// ---------------- launcher ----------------
extern "C" void kernel_launch(void* const* d_in, const int* in_sizes, int n_in,
                              void* d_out, int out_size)
{
    const float* x     = (const float*)d_in[0];
    const float* W_tok = (const float*)d_in[1];
    const float* W_lvl = (const float*)d_in[2];
    const float* W_out = (const float*)d_in[3];
    float* out = (float*)d_out;

    __half *xh, *xl, *wth, *woh, *wlh, *wll, *thh;
    float *phi, *tscale, *part; float2* sc;
    cudaGetSymbolAddress((void**)&xh,  g_xh);   cudaGetSymbolAddress((void**)&xl,  g_xl);
    cudaGetSymbolAddress((void**)&wth, g_wth);  cudaGetSymbolAddress((void**)&woh, g_woh);
    cudaGetSymbolAddress((void**)&wlh, g_wlh);  cudaGetSymbolAddress((void**)&wll, g_wll);
    cudaGetSymbolAddress((void**)&thh, g_thh);
    cudaGetSymbolAddress((void**)&part,   g_part);
    cudaGetSymbolAddress((void**)&phi,    g_phi);
    cudaGetSymbolAddress((void**)&tscale, g_tscale);
    cudaGetSymbolAddress((void**)&sc,     g_sc);

    const int SMEM_MAIN  = 2 * STG4;            // 81920 (covers 3*STG2=61440 too)
    const int SMEM_G3    = 3 * STG2;            // 61440
    const int SMEM_BFLY  = 4096 * BSTR * 4;     // 196608
    cudaFuncSetAttribute(f16_gemm_main, cudaFuncAttributeMaxDynamicSharedMemorySize, SMEM_MAIN);
    cudaFuncSetAttribute(f16_gemm1, cudaFuncAttributeMaxDynamicSharedMemorySize, SMEM_G3);
    cudaFuncSetAttribute(butterfly_fused, cudaFuncAttributeMaxDynamicSharedMemorySize, SMEM_BFLY);

    // 1) all operand conversions in one kernel
    cvt_all<<<(N_ALL + 255) / 256, 256>>>((const float4*)x, (const float4*)W_tok,
                                          (const float4*)W_out, (const float4*)W_lvl,
                                          (uint2*)xh, (uint2*)xl, (uint2*)wth,
                                          (uint2*)woh, (uint2*)wlh, (uint2*)wll);

    // 2) merged GEMM: theta (fp16 out + ssq partials) + phi
    f16_gemm_main<<<dim3(18, Mc / 128), 128, SMEM_MAIN>>>(xh, xl, wth, thh, part,
                                                          wlh, wll, phi);

    // 3) fused theta-scale finish + RMSNorm(phi) + sincos
    phi_rms_sincos<<<Mc, 192>>>(phi, part, tscale, sc);

    // 4) fused butterfly (12 levels, applies tscale), fp16 in-place, prefetched sc
    butterfly_fused<<<dim3(16, Hc, 2), 512, SMEM_BFLY>>>(thh, tscale, sc);

    // 5) y = theta @ W_out^T  (single-pass fp16)
    f16_gemm1<<<dim3(16, Mc / 128), 128, SMEM_G3>>>(thh, woh, out);
}

// round 16
// speedup vs baseline: 1.4985x; 1.4985x over previous
#include <cuda_runtime.h>
#include <cuda_fp16.h>
#include <cstdint>
#include <math.h>

// ---------------- problem shapes (fixed) ----------------
#define Tc   4096
#define Dc   2048
#define Hc   16
#define Lc   12
#define LHc  192
#define Mc   8192          // B*T
#define KKc  2048          // GEMM K
#define EPSV 1.1920929e-07f
#define INVSQRT2 0.70710678118654752440f

// ---------------- scratch (static device globals; zero-initialized) ----------
__device__ __half g_xh [(size_t)Mc * Dc];      // x fp16 hi
__device__ __half g_xl [(size_t)Mc * Dc];      // x fp16 lo (phi path only)
__device__ __half g_wth[(size_t)Dc * Dc];      // W_tok fp16
__device__ __half g_woh[(size_t)Dc * Dc];      // W_out fp16
__device__ __half g_wlh[(size_t)256 * Dc];     // W_lvl fp16 hi, padded 192->256 rows
__device__ __half g_wll[(size_t)256 * Dc];     // W_lvl fp16 lo
__device__ __half g_thh[(size_t)Mc * Dc];      // theta fp16 (pre-norm, then in-place butterfly)
__device__ float g_part  [(size_t)Mc * 32];    // per-(row, n-slab) sum-of-squares partials
__device__ float g_phi   [(size_t)Mc * 256];   // padded cols
__device__ float g_tscale[(size_t)Mc];
__device__ float2 g_sc   [(size_t)2 * Hc * Lc * Tc];

// ---------------- PTX helpers ----------------
__device__ __forceinline__ uint32_t smem_u32(const void* p) {
    uint32_t a;
    asm("{ .reg .u64 t; cvta.to.shared.u64 t, %1; cvt.u32.u64 %0, t; }" : "=r"(a) : "l"(p));
    return a;
}
__device__ __forceinline__ void cp_async16(uint32_t s, const void* g) {
    asm volatile("cp.async.cg.shared.global [%0], [%1], 16;" :: "r"(s), "l"(g));
}
#define CP_COMMIT() asm volatile("cp.async.commit_group;" ::: "memory")
#define CP_WAIT1()  asm volatile("cp.async.wait_group 1;" ::: "memory")
#define CP_WAIT0()  asm volatile("cp.async.wait_group 0;" ::: "memory")

#define LDSM4(d0,d1,d2,d3,a) \
    asm volatile("ldmatrix.sync.aligned.m8n8.x4.shared.b16 {%0,%1,%2,%3}, [%4];" \
        : "=r"(d0), "=r"(d1), "=r"(d2), "=r"(d3) : "r"(a))

#define MMA_F16(c, a0,a1,a2,a3, b0,b1) \
    asm volatile("mma.sync.aligned.m16n8k16.row.col.f32.f16.f16.f32 " \
        "{%0,%1,%2,%3}, {%4,%5,%6,%7}, {%8,%9}, {%0,%1,%2,%3};" \
        : "+f"((c)[0]), "+f"((c)[1]), "+f"((c)[2]), "+f"((c)[3]) \
        : "r"(a0), "r"(a1), "r"(a2), "r"(a3), "r"(b0), "r"(b1))

#define RB    80                        // smem row bytes: 32 halves (64B) + 16B pad
#define TILE  (128 * RB)                // 10240 B per operand tile
#define STG2  (2 * TILE)                // 20480 (single-pass stage: A,B)
#define STG4  (4 * TILE)                // 40960 (phi stage: Ah,Al,Bh,Bl)
#define NCH   (KKc / 32)                // 64 chunks

// ============== merged GEMM: theta (1-pass, fp16 out + ssq) + phi (3-pass) ===
__global__ __launch_bounds__(128, 2)
void f16_gemm_main(const __half* __restrict__ Ah, const __half* __restrict__ Al,
                   const __half* __restrict__ B, __half* __restrict__ Ct,
                   float* __restrict__ part,
                   const __half* __restrict__ Bh2, const __half* __restrict__ Bl2,
                   float* __restrict__ C2)
{
    extern __shared__ char smem[];
    const uint32_t sb = smem_u32(smem);
    const int tid  = threadIdx.x;
    const int wid  = tid >> 5;
    const int lane = tid & 31;
    const int m0 = blockIdx.y * 128;
    const int wm = (wid & 1) * 64;
    const int wn = (wid >> 1) * 64;
    const bool primary = (int)blockIdx.x < 16;

    const int g = lane >> 3, r = lane & 7;
    const int bTile = primary ? 1 : 2;      // B tile index within stage
    uint32_t aOff[4], bOff[4];
    #pragma unroll
    for (int mt = 0; mt < 4; mt++)
        aOff[mt] = (uint32_t)((wm + mt * 16 + (g & 1) * 8 + r) * RB + (g >> 1) * 16);
    #pragma unroll
    for (int nt2 = 0; nt2 < 4; nt2++)
        bOff[nt2] = (uint32_t)(bTile * TILE + (wn + nt2 * 16 + (g >> 1) * 8 + r) * RB + (g & 1) * 16);

    float acc[4][8][4];
    #pragma unroll
    for (int i = 0; i < 4; i++)
        #pragma unroll
        for (int j = 0; j < 8; j++)
            #pragma unroll
            for (int v = 0; v < 4; v++) acc[i][j][v] = 0.f;

    if (primary) {
        // ---------------- theta: 3-stage, 1 pass, 2 tiles ----------------
        const int n0 = blockIdx.x * 128;
        const __half* tp[2] = { Ah + (size_t)m0 * KKc, B + (size_t)n0 * KKc };

        auto load_stage = [&](int c, int st) {
            const uint32_t base = sb + st * STG2;
            #pragma unroll
            for (int t = 0; t < 2; t++) {
                const __half* src = tp[t] + c * 32;
                #pragma unroll
                for (int i = 0; i < 4; i++) {
                    const int idx = tid + i * 128;
                    const int row = idx >> 2;
                    const int ch  = idx & 3;
                    cp_async16(base + t * TILE + row * RB + ch * 16,
                               src + (size_t)row * KKc + ch * 8);
                }
            }
            CP_COMMIT();
        };

        load_stage(0, 0);
        load_stage(1, 1);

        for (int c = 0; c < NCH; c++) {
            if (c + 1 < NCH) CP_WAIT1(); else CP_WAIT0();
            __syncthreads();
            if (c + 2 < NCH) load_stage(c + 2, (c + 2) % 3);

            const uint32_t stb = sb + (c % 3) * STG2;
            #pragma unroll
            for (int ks = 0; ks < 2; ks++) {
                const uint32_t ko = ks * 32;
                uint32_t ah[4][4], bh[4][4];
                #pragma unroll
                for (int mt = 0; mt < 4; mt++)
                    LDSM4(ah[mt][0], ah[mt][1], ah[mt][2], ah[mt][3], stb + aOff[mt] + ko);
                #pragma unroll
                for (int nt2 = 0; nt2 < 4; nt2++)
                    LDSM4(bh[nt2][0], bh[nt2][1], bh[nt2][2], bh[nt2][3], stb + bOff[nt2] + ko);
                #pragma unroll
                for (int mt = 0; mt < 4; mt++)
                    #pragma unroll
                    for (int nt = 0; nt < 8; nt++) {
                        const uint32_t* bb = &bh[nt >> 1][(nt & 1) * 2];
                        MMA_F16(acc[mt][nt], ah[mt][0], ah[mt][1], ah[mt][2], ah[mt][3], bb[0], bb[1]);
                    }
            }
        }

        // ---- epilogue: fp16 theta + deterministic ssq partials ----
        const int slot = blockIdx.x * 2 + (wn >> 6);
        #pragma unroll
        for (int mt = 0; mt < 4; mt++) {
            const int m = m0 + wm + mt * 16 + (lane >> 2);
            float ss0 = 0.f, ss1 = 0.f;
            #pragma unroll
            for (int nt = 0; nt < 8; nt++) {
                const int n = n0 + wn + nt * 8 + (lane & 3) * 2;
                const float a0 = acc[mt][nt][0], a1 = acc[mt][nt][1];
                const float a2 = acc[mt][nt][2], a3 = acc[mt][nt][3];
                *(__half2*)(Ct + (size_t)m * Dc + n)       = __floats2half2_rn(a0, a1);
                *(__half2*)(Ct + (size_t)(m + 8) * Dc + n) = __floats2half2_rn(a2, a3);
                ss0 = fmaf(a0, a0, fmaf(a1, a1, ss0));
                ss1 = fmaf(a2, a2, fmaf(a3, a3, ss1));
            }
            ss0 += __shfl_xor_sync(0xffffffffu, ss0, 1);
            ss0 += __shfl_xor_sync(0xffffffffu, ss0, 2);
            ss1 += __shfl_xor_sync(0xffffffffu, ss1, 1);
            ss1 += __shfl_xor_sync(0xffffffffu, ss1, 2);
            if ((lane & 3) == 0) {
                part[(size_t)m * 32 + slot]       = ss0;
                part[(size_t)(m + 8) * 32 + slot] = ss1;
            }
        }
    } else {
        // ---------------- phi: 2-stage, 3 passes, 4 tiles ----------------
        const int n0 = ((int)blockIdx.x - 16) * 128;
        const bool active = (n0 + wn) < LHc;       // skip pure-padding warp columns
        const __half* tp[4] = { Ah + (size_t)m0 * KKc, Al + (size_t)m0 * KKc,
                                Bh2 + (size_t)n0 * KKc, Bl2 + (size_t)n0 * KKc };

        auto load_stage4 = [&](int c, int st) {
            const uint32_t base = sb + st * STG4;
            #pragma unroll
            for (int i = 0; i < 16; i++) {
                const int idx = tid + i * 128;       // 0..2047
                const int t   = idx >> 9;
                const int rem = idx & 511;
                const int row = rem >> 2;
                const int ch  = rem & 3;
                cp_async16(base + t * TILE + row * RB + ch * 16,
                           tp[t] + (size_t)row * KKc + c * 32 + ch * 8);
            }
            CP_COMMIT();
        };

        load_stage4(0, 0);

        for (int c = 0; c < NCH; c++) {
            if (c + 1 < NCH) { load_stage4(c + 1, (c + 1) & 1); CP_WAIT1(); }
            else             { CP_WAIT0(); }
            __syncthreads();

            const uint32_t stb = sb + (c & 1) * STG4;
            if (active) {
                #pragma unroll
                for (int ks = 0; ks < 2; ks++) {
                    const uint32_t ko = ks * 32;
                    uint32_t ah[4][4], bh[4][4], xx[4][4];

                    #pragma unroll
                    for (int mt = 0; mt < 4; mt++)
                        LDSM4(ah[mt][0], ah[mt][1], ah[mt][2], ah[mt][3], stb + aOff[mt] + ko);
                    #pragma unroll
                    for (int nt2 = 0; nt2 < 4; nt2++)
                        LDSM4(bh[nt2][0], bh[nt2][1], bh[nt2][2], bh[nt2][3], stb + bOff[nt2] + ko);
                    #pragma unroll
                    for (int mt = 0; mt < 4; mt++)
                        #pragma unroll
                        for (int nt = 0; nt < 8; nt++) {
                            const uint32_t* bb = &bh[nt >> 1][(nt & 1) * 2];
                            MMA_F16(acc[mt][nt], ah[mt][0], ah[mt][1], ah[mt][2], ah[mt][3], bb[0], bb[1]);
                        }

                    #pragma unroll
                    for (int mt = 0; mt < 4; mt++)
                        LDSM4(xx[mt][0], xx[mt][1], xx[mt][2], xx[mt][3], stb + TILE + aOff[mt] + ko);
                    #pragma unroll
                    for (int mt = 0; mt < 4; mt++)
                        #pragma unroll
                        for (int nt = 0; nt < 8; nt++) {
                            const uint32_t* bb = &bh[nt >> 1][(nt & 1) * 2];
                            MMA_F16(acc[mt][nt], xx[mt][0], xx[mt][1], xx[mt][2], xx[mt][3], bb[0], bb[1]);
                        }

                    #pragma unroll
                    for (int nt2 = 0; nt2 < 4; nt2++)
                        LDSM4(xx[nt2][0], xx[nt2][1], xx[nt2][2], xx[nt2][3], stb + TILE + bOff[nt2] + ko);
                    #pragma unroll
                    for (int mt = 0; mt < 4; mt++)
                        #pragma unroll
                        for (int nt = 0; nt < 8; nt++) {
                            const uint32_t* bb = &xx[nt >> 1][(nt & 1) * 2];
                            MMA_F16(acc[mt][nt], ah[mt][0], ah[mt][1], ah[mt][2], ah[mt][3], bb[0], bb[1]);
                        }
                }
            }
            __syncthreads();
        }

        if (active) {
            #pragma unroll
            for (int mt = 0; mt < 4; mt++) {
                const int m = m0 + wm + mt * 16 + (lane >> 2);
                #pragma unroll
                for (int nt = 0; nt < 8; nt++) {
                    const int n = n0 + wn + nt * 8 + (lane & 3) * 2;
                    *(float2*)(C2 + (size_t)m * 256 + n)       = make_float2(acc[mt][nt][0], acc[mt][nt][1]);
                    *(float2*)(C2 + (size_t)(m + 8) * 256 + n) = make_float2(acc[mt][nt][2], acc[mt][nt][3]);
                }
            }
        }
    }
}

// ================= GEMM3: single-pass fp16 ==================
__global__ __launch_bounds__(128, 2)
void f16_gemm1(const __half* __restrict__ A, const __half* __restrict__ B,
               float* __restrict__ C)
{
    extern __shared__ char smem[];
    const uint32_t sb = smem_u32(smem);
    const int tid  = threadIdx.x;
    const int wid  = tid >> 5;
    const int lane = tid & 31;
    const int m0 = blockIdx.y * 128;
    const int n0 = blockIdx.x * 128;
    const int wm = (wid & 1) * 64;
    const int wn = (wid >> 1) * 64;

    const int g = lane >> 3, r = lane & 7;
    uint32_t aOff[4], bOff[4];
    #pragma unroll
    for (int mt = 0; mt < 4; mt++)
        aOff[mt] = (uint32_t)((wm + mt * 16 + (g & 1) * 8 + r) * RB + (g >> 1) * 16);
    #pragma unroll
    for (int nt2 = 0; nt2 < 4; nt2++)
        bOff[nt2] = (uint32_t)(TILE + (wn + nt2 * 16 + (g >> 1) * 8 + r) * RB + (g & 1) * 16);

    float acc[4][8][4];
    #pragma unroll
    for (int i = 0; i < 4; i++)
        #pragma unroll
        for (int j = 0; j < 8; j++)
            #pragma unroll
            for (int v = 0; v < 4; v++) acc[i][j][v] = 0.f;

    const __half* tp[2] = { A + (size_t)m0 * KKc, B + (size_t)n0 * KKc };

    auto load_stage = [&](int c, int st) {
        const uint32_t base = sb + st * STG2;
        #pragma unroll
        for (int t = 0; t < 2; t++) {
            const __half* src = tp[t] + c * 32;
            #pragma unroll
            for (int i = 0; i < 4; i++) {
                const int idx = tid + i * 128;
                const int row = idx >> 2;
                const int ch  = idx & 3;
                cp_async16(base + t * TILE + row * RB + ch * 16,
                           src + (size_t)row * KKc + ch * 8);
            }
        }
        CP_COMMIT();
    };

    load_stage(0, 0);
    load_stage(1, 1);

    for (int c = 0; c < NCH; c++) {
        if (c + 1 < NCH) CP_WAIT1(); else CP_WAIT0();
        __syncthreads();
        if (c + 2 < NCH) load_stage(c + 2, (c + 2) % 3);

        const uint32_t stb = sb + (c % 3) * STG2;
        #pragma unroll
        for (int ks = 0; ks < 2; ks++) {
            const uint32_t ko = ks * 32;
            uint32_t ah[4][4], bh[4][4];
            #pragma unroll
            for (int mt = 0; mt < 4; mt++)
                LDSM4(ah[mt][0], ah[mt][1], ah[mt][2], ah[mt][3], stb + aOff[mt] + ko);
            #pragma unroll
            for (int nt2 = 0; nt2 < 4; nt2++)
                LDSM4(bh[nt2][0], bh[nt2][1], bh[nt2][2], bh[nt2][3], stb + bOff[nt2] + ko);
            #pragma unroll
            for (int mt = 0; mt < 4; mt++)
                #pragma unroll
                for (int nt = 0; nt < 8; nt++) {
                    const uint32_t* bb = &bh[nt >> 1][(nt & 1) * 2];
                    MMA_F16(acc[mt][nt], ah[mt][0], ah[mt][1], ah[mt][2], ah[mt][3], bb[0], bb[1]);
                }
        }
    }

    #pragma unroll
    for (int mt = 0; mt < 4; mt++) {
        const int m = m0 + wm + mt * 16 + (lane >> 2);
        #pragma unroll
        for (int nt = 0; nt < 8; nt++) {
            const int n = n0 + wn + nt * 8 + (lane & 3) * 2;
            *(float2*)(C + (size_t)m * Dc + n)       = make_float2(acc[mt][nt][0], acc[mt][nt][1]);
            *(float2*)(C + (size_t)(m + 8) * Dc + n) = make_float2(acc[mt][nt][2], acc[mt][nt][3]);
        }
    }
}

// ---------------- fused operand conversions (one kernel) ----------------
__device__ __forceinline__ void split4(float4 v, uint2* H, uint2* L, int i) {
    __half h0 = __float2half_rn(v.x), h1 = __float2half_rn(v.y);
    __half h2 = __float2half_rn(v.z), h3 = __float2half_rn(v.w);
    __half l0 = __float2half_rn(v.x - __half2float(h0));
    __half l1 = __float2half_rn(v.y - __half2float(h1));
    __half l2 = __float2half_rn(v.z - __half2float(h2));
    __half l3 = __float2half_rn(v.w - __half2float(h3));
    __half2 ha = {h0, h1}, hb = {h2, h3}, la = {l0, l1}, lb = {l2, l3};
    H[i] = make_uint2(*(uint32_t*)&ha, *(uint32_t*)&hb);
    L[i] = make_uint2(*(uint32_t*)&la, *(uint32_t*)&lb);
}
__device__ __forceinline__ void cvt4(float4 v, uint2* H, int i) {
    __half2 a = __floats2half2_rn(v.x, v.y);
    __half2 b = __floats2half2_rn(v.z, v.w);
    H[i] = make_uint2(*(uint32_t*)&a, *(uint32_t*)&b);
}

#define N_X  (Mc * Dc / 4)
#define N_W  (Dc * Dc / 4)
#define N_L  (LHc * Dc / 4)
#define N_ALL (N_X + 2 * N_W + N_L)

__global__ void cvt_all(const float4* __restrict__ x, const float4* __restrict__ wt,
                        const float4* __restrict__ wo, const float4* __restrict__ wl,
                        uint2* __restrict__ xh, uint2* __restrict__ xl,
                        uint2* __restrict__ wth, uint2* __restrict__ woh,
                        uint2* __restrict__ wlh, uint2* __restrict__ wll)
{
    int i = blockIdx.x * blockDim.x + threadIdx.x;
    if (i < N_X) {
        split4(x[i], xh, xl, i);
    } else if (i < N_X + N_W) {
        int j = i - N_X;
        cvt4(wt[j], wth, j);
    } else if (i < N_X + 2 * N_W) {
        int j = i - N_X - N_W;
        cvt4(wo[j], woh, j);
    } else if (i < N_ALL) {
        int j = i - N_X - 2 * N_W;
        split4(wl[j], wlh, wll, j);
    }
}

// ------- fused: theta-scale finish + RMSNorm(phi) + sincos transpose -------
__global__ __launch_bounds__(192)
void phi_rms_sincos(const float* __restrict__ phi, const float* __restrict__ part,
                    float* __restrict__ tscale, float2* __restrict__ sc)
{
    const int row = blockIdx.x;            // b*4096 + t
    const int t   = row & (Tc - 1);
    const int b   = row >> 12;
    const int j   = threadIdx.x;           // 0..191

    // warp 0: finish theta rms scale from 32 slab partials
    if (j < 32) {
        float ss = part[(size_t)row * 32 + j];
        #pragma unroll
        for (int o = 16; o > 0; o >>= 1) ss += __shfl_xor_sync(0xffffffffu, ss, o);
        if (j == 0) tscale[row] = rsqrtf(ss / (float)Dc + EPSV);
    }

    const float v = phi[(size_t)row * 256 + j];
    float ss = v * v;
    #pragma unroll
    for (int o = 16; o > 0; o >>= 1) ss += __shfl_xor_sync(0xffffffffu, ss, o);
    __shared__ float red[6];
    const int warp = j >> 5, lane = j & 31;
    if (lane == 0) red[warp] = ss;
    __syncthreads();
    float tot = red[0] + red[1] + red[2] + red[3] + red[4] + red[5];
    const float rs = rsqrtf(tot / (float)LHc + EPSV);

    float s, c;
    sincosf(v * rs, &s, &c);
    const int l = j >> 4, h = j & 15;
    sc[((size_t)(b * Hc + h) * Lc + l) * Tc + t] = make_float2(c * INVSQRT2, s * INVSQRT2);
}

// ---------------- fused 12-level butterfly (fp16 in-place) ----------------
#define BSTR 12
__global__ __launch_bounds__(512, 1)
void butterfly_fused(__half* __restrict__ Th, const float* __restrict__ tscale,
                     const float2* __restrict__ sc)
{
    extern __shared__ float th[];   // [4096][BSTR]
    const int ds  = blockIdx.x;     // 0..15
    const int h   = blockIdx.y;     // 0..15
    const int b   = blockIdx.z;     // 0..1
    const int tid = threadIdx.x;
    const int cb  = h * 128 + ds * 8;
    const size_t rowbase = (size_t)b * Tc;

    float cur[8][8];

    #pragma unroll
    for (int k = 0; k < 8; k++) {
        const int t = tid + k * 512;
        const float scl = tscale[rowbase + t];
        uint4 raw = *(const uint4*)(Th + (rowbase + t) * Dc + cb);
        const __half2* hp = (const __half2*)&raw;
        #pragma unroll
        for (int p = 0; p < 4; p++) {
            float2 f = __half22float2(hp[p]);
            cur[k][p * 2]     = f.x * scl;
            cur[k][p * 2 + 1] = f.y * scl;
        }
        float* s = &th[t * BSTR];
        *(float4*)s       = make_float4(cur[k][0], cur[k][1], cur[k][2], cur[k][3]);
        *(float4*)(s + 4) = make_float4(cur[k][4], cur[k][5], cur[k][6], cur[k][7]);
    }
    __syncthreads();

    const float2* scb = sc + (size_t)(b * Hc + h) * Lc * Tc;
    for (int l = 0; l < Lc; l++) {
        const int step = 1 << l;
        #pragma unroll
        for (int k = 0; k < 8; k++) {
            const int t = tid + k * 512;
            const float2 w = scb[l * Tc + t];
            float4 p0 = make_float4(0.f, 0.f, 0.f, 0.f);
            float4 p1 = p0;
            if (t >= step) {
                const float* ps = &th[(t - step) * BSTR];
                p0 = *(const float4*)ps;
                p1 = *(const float4*)(ps + 4);
            }
            cur[k][0] = fmaf(w.x, cur[k][0], w.y * p0.x);
            cur[k][1] = fmaf(w.x, cur[k][1], w.y * p0.y);
            cur[k][2] = fmaf(w.x, cur[k][2], w.y * p0.z);
            cur[k][3] = fmaf(w.x, cur[k][3], w.y * p0.w);
            cur[k][4] = fmaf(w.x, cur[k][4], w.y * p1.x);
            cur[k][5] = fmaf(w.x, cur[k][5], w.y * p1.y);
            cur[k][6] = fmaf(w.x, cur[k][6], w.y * p1.z);
            cur[k][7] = fmaf(w.x, cur[k][7], w.y * p1.w);
        }
        __syncthreads();                 // all reads of old level done
        if (l < Lc - 1) {
            #pragma unroll
            for (int k = 0; k < 8; k++) {
                float* s = &th[(tid + k * 512) * BSTR];
                *(float4*)s       = make_float4(cur[k][0], cur[k][1], cur[k][2], cur[k][3]);
                *(float4*)(s + 4) = make_float4(cur[k][4], cur[k][5], cur[k][6], cur[k][7]);
            }
            __syncthreads();             // new level visible
        }
    }

    #pragma unroll
    for (int k = 0; k < 8; k++) {
        const int t = tid + k * 512;
        __half2 h0 = __floats2half2_rn(cur[k][0], cur[k][1]);
        __half2 h1 = __floats2half2_rn(cur[k][2], cur[k][3]);
        __half2 h2 = __floats2half2_rn(cur[k][4], cur[k][5]);
        __half2 h3 = __floats2half2_rn(cur[k][6], cur[k][7]);
        uint4 o;
        o.x = *(uint32_t*)&h0; o.y = *(uint32_t*)&h1;
        o.z = *(uint32_t*)&h2; o.w = *(uint32_t*)&h3;
        *(uint4*)(Th + (rowbase + t) * Dc + cb) = o;
    }
}

// ---------------- launcher ----------------
extern "C" void kernel_launch(void* const* d_in, const int* in_sizes, int n_in,
                              void* d_out, int out_size)
{
    const float* x     = (const float*)d_in[0];
    const float* W_tok = (const float*)d_in[1];
    const float* W_lvl = (const float*)d_in[2];
    const float* W_out = (const float*)d_in[3];
    float* out = (float*)d_out;

    __half *xh, *xl, *wth, *woh, *wlh, *wll, *thh;
    float *phi, *tscale, *part; float2* sc;
    cudaGetSymbolAddress((void**)&xh,  g_xh);   cudaGetSymbolAddress((void**)&xl,  g_xl);
    cudaGetSymbolAddress((void**)&wth, g_wth);  cudaGetSymbolAddress((void**)&woh, g_woh);
    cudaGetSymbolAddress((void**)&wlh, g_wlh);  cudaGetSymbolAddress((void**)&wll, g_wll);
    cudaGetSymbolAddress((void**)&thh, g_thh);
    cudaGetSymbolAddress((void**)&part,   g_part);
    cudaGetSymbolAddress((void**)&phi,    g_phi);
    cudaGetSymbolAddress((void**)&tscale, g_tscale);
    cudaGetSymbolAddress((void**)&sc,     g_sc);

    const int SMEM_MAIN  = 2 * STG4;            // 81920 (covers 3*STG2=61440 too)
    const int SMEM_G3    = 3 * STG2;            // 61440
    const int SMEM_BFLY  = 4096 * BSTR * 4;     // 196608
    cudaFuncSetAttribute(f16_gemm_main, cudaFuncAttributeMaxDynamicSharedMemorySize, SMEM_MAIN);
    cudaFuncSetAttribute(f16_gemm1, cudaFuncAttributeMaxDynamicSharedMemorySize, SMEM_G3);
    cudaFuncSetAttribute(butterfly_fused, cudaFuncAttributeMaxDynamicSharedMemorySize, SMEM_BFLY);

    // 1) all operand conversions in one kernel
    cvt_all<<<(N_ALL + 255) / 256, 256>>>((const float4*)x, (const float4*)W_tok,
                                          (const float4*)W_out, (const float4*)W_lvl,
                                          (uint2*)xh, (uint2*)xl, (uint2*)wth,
                                          (uint2*)woh, (uint2*)wlh, (uint2*)wll);

    // 2) merged GEMM: theta (fp16 out + ssq partials) + phi
    f16_gemm_main<<<dim3(18, Mc / 128), 128, SMEM_MAIN>>>(xh, xl, wth, thh, part,
                                                          wlh, wll, phi);

    // 3) fused theta-scale finish + RMSNorm(phi) + sincos
    phi_rms_sincos<<<Mc, 192>>>(phi, part, tscale, sc);

    // 4) fused butterfly (12 levels, applies tscale), fp16 in-place
    butterfly_fused<<<dim3(16, Hc, 2), 512, SMEM_BFLY>>>(thh, tscale, sc);

    // 5) y = theta @ W_out^T  (single-pass fp16)
    f16_gemm1<<<dim3(16, Mc / 128), 128, SMEM_G3>>>(thh, woh, out);
}

// round 17
// speedup vs baseline: 1.5131x; 1.0098x over previous
#include <cuda_runtime.h>
#include <cuda_fp16.h>
#include <cstdint>
#include <math.h>

// ---------------- problem shapes (fixed) ----------------
#define Tc   4096
#define Dc   2048
#define Hc   16
#define Lc   12
#define LHc  192
#define Mc   8192          // B*T
#define KKc  2048          // GEMM K
#define EPSV 1.1920929e-07f
#define INVSQRT2 0.70710678118654752440f

// ---------------- scratch (static device globals; zero-initialized) ----------
__device__ __half g_xh [(size_t)Mc * Dc];      // x fp16 hi
__device__ __half g_xl [(size_t)Mc * Dc];      // x fp16 lo (phi path only)
__device__ __half g_wth[(size_t)Dc * Dc];      // W_tok fp16
__device__ __half g_woh[(size_t)Dc * Dc];      // W_out fp16
__device__ __half g_wlh[(size_t)256 * Dc];     // W_lvl fp16 hi, padded 192->256 rows
__device__ __half g_wll[(size_t)256 * Dc];     // W_lvl fp16 lo
__device__ __half g_thh[(size_t)Mc * Dc];      // theta fp16 (pre-norm, then in-place butterfly)
__device__ float g_part  [(size_t)Mc * 32];    // per-(row, n-slab) sum-of-squares partials
__device__ float g_phi   [(size_t)Mc * 256];   // padded cols
__device__ float g_tscale[(size_t)Mc];
__device__ float2 g_sc   [(size_t)2 * Hc * Lc * Tc];

// ---------------- PTX helpers ----------------
__device__ __forceinline__ uint32_t smem_u32(const void* p) {
    uint32_t a;
    asm("{ .reg .u64 t; cvta.to.shared.u64 t, %1; cvt.u32.u64 %0, t; }" : "=r"(a) : "l"(p));
    return a;
}
__device__ __forceinline__ void cp_async16(uint32_t s, const void* g) {
    asm volatile("cp.async.cg.shared.global [%0], [%1], 16;" :: "r"(s), "l"(g));
}
#define CP_COMMIT() asm volatile("cp.async.commit_group;" ::: "memory")
#define CP_WAIT1()  asm volatile("cp.async.wait_group 1;" ::: "memory")
#define CP_WAIT0()  asm volatile("cp.async.wait_group 0;" ::: "memory")

#define LDSM4(d0,d1,d2,d3,a) \
    asm volatile("ldmatrix.sync.aligned.m8n8.x4.shared.b16 {%0,%1,%2,%3}, [%4];" \
        : "=r"(d0), "=r"(d1), "=r"(d2), "=r"(d3) : "r"(a))

#define MMA_F16(c, a0,a1,a2,a3, b0,b1) \
    asm volatile("mma.sync.aligned.m16n8k16.row.col.f32.f16.f16.f32 " \
        "{%0,%1,%2,%3}, {%4,%5,%6,%7}, {%8,%9}, {%0,%1,%2,%3};" \
        : "+f"((c)[0]), "+f"((c)[1]), "+f"((c)[2]), "+f"((c)[3]) \
        : "r"(a0), "r"(a1), "r"(a2), "r"(a3), "r"(b0), "r"(b1))

#define RB    80                        // smem row bytes: 32 halves (64B) + 16B pad
#define TILE  (128 * RB)                // 10240 B per operand tile
#define STG2  (2 * TILE)                // 20480 (single-pass stage: A,B)
#define STG4  (4 * TILE)                // 40960 (phi stage: Ah,Al,Bh,Bl)
#define NCH   (KKc / 32)                // 64 chunks

// ============== merged GEMM: theta (1-pass, fp16 out + ssq) + phi (3-pass) ===
__global__ __launch_bounds__(128, 2)
void f16_gemm_main(const __half* __restrict__ Ah, const __half* __restrict__ Al,
                   const __half* __restrict__ B, __half* __restrict__ Ct,
                   float* __restrict__ part,
                   const __half* __restrict__ Bh2, const __half* __restrict__ Bl2,
                   float* __restrict__ C2)
{
    extern __shared__ char smem[];
    const uint32_t sb = smem_u32(smem);
    const int tid  = threadIdx.x;
    const int wid  = tid >> 5;
    const int lane = tid & 31;
    const int m0 = blockIdx.y * 128;
    const int wm = (wid & 1) * 64;
    const int wn = (wid >> 1) * 64;
    const bool primary = (int)blockIdx.x < 16;

    const int g = lane >> 3, r = lane & 7;
    const int bTile = primary ? 1 : 2;      // B tile index within stage
    uint32_t aOff[4], bOff[4];
    #pragma unroll
    for (int mt = 0; mt < 4; mt++)
        aOff[mt] = (uint32_t)((wm + mt * 16 + (g & 1) * 8 + r) * RB + (g >> 1) * 16);
    #pragma unroll
    for (int nt2 = 0; nt2 < 4; nt2++)
        bOff[nt2] = (uint32_t)(bTile * TILE + (wn + nt2 * 16 + (g >> 1) * 8 + r) * RB + (g & 1) * 16);

    float acc[4][8][4];
    #pragma unroll
    for (int i = 0; i < 4; i++)
        #pragma unroll
        for (int j = 0; j < 8; j++)
            #pragma unroll
            for (int v = 0; v < 4; v++) acc[i][j][v] = 0.f;

    if (primary) {
        // ---------------- theta: 3-stage, 1 pass, 2 tiles ----------------
        const int n0 = blockIdx.x * 128;
        const __half* tp[2] = { Ah + (size_t)m0 * KKc, B + (size_t)n0 * KKc };

        auto load_stage = [&](int c, int st) {
            const uint32_t base = sb + st * STG2;
            #pragma unroll
            for (int t = 0; t < 2; t++) {
                const __half* src = tp[t] + c * 32;
                #pragma unroll
                for (int i = 0; i < 4; i++) {
                    const int idx = tid + i * 128;
                    const int row = idx >> 2;
                    const int ch  = idx & 3;
                    cp_async16(base + t * TILE + row * RB + ch * 16,
                               src + (size_t)row * KKc + ch * 8);
                }
            }
            CP_COMMIT();
        };

        load_stage(0, 0);
        load_stage(1, 1);

        for (int c = 0; c < NCH; c++) {
            if (c + 1 < NCH) CP_WAIT1(); else CP_WAIT0();
            __syncthreads();
            if (c + 2 < NCH) load_stage(c + 2, (c + 2) % 3);

            const uint32_t stb = sb + (c % 3) * STG2;
            #pragma unroll
            for (int ks = 0; ks < 2; ks++) {
                const uint32_t ko = ks * 32;
                uint32_t ah[4][4], bh[4][4];
                #pragma unroll
                for (int mt = 0; mt < 4; mt++)
                    LDSM4(ah[mt][0], ah[mt][1], ah[mt][2], ah[mt][3], stb + aOff[mt] + ko);
                #pragma unroll
                for (int nt2 = 0; nt2 < 4; nt2++)
                    LDSM4(bh[nt2][0], bh[nt2][1], bh[nt2][2], bh[nt2][3], stb + bOff[nt2] + ko);
                #pragma unroll
                for (int mt = 0; mt < 4; mt++)
                    #pragma unroll
                    for (int nt = 0; nt < 8; nt++) {
                        const uint32_t* bb = &bh[nt >> 1][(nt & 1) * 2];
                        MMA_F16(acc[mt][nt], ah[mt][0], ah[mt][1], ah[mt][2], ah[mt][3], bb[0], bb[1]);
                    }
            }
        }

        // ---- epilogue: fp16 theta + deterministic ssq partials ----
        const int slot = blockIdx.x * 2 + (wn >> 6);
        #pragma unroll
        for (int mt = 0; mt < 4; mt++) {
            const int m = m0 + wm + mt * 16 + (lane >> 2);
            float ss0 = 0.f, ss1 = 0.f;
            #pragma unroll
            for (int nt = 0; nt < 8; nt++) {
                const int n = n0 + wn + nt * 8 + (lane & 3) * 2;
                const float a0 = acc[mt][nt][0], a1 = acc[mt][nt][1];
                const float a2 = acc[mt][nt][2], a3 = acc[mt][nt][3];
                *(__half2*)(Ct + (size_t)m * Dc + n)       = __floats2half2_rn(a0, a1);
                *(__half2*)(Ct + (size_t)(m + 8) * Dc + n) = __floats2half2_rn(a2, a3);
                ss0 = fmaf(a0, a0, fmaf(a1, a1, ss0));
                ss1 = fmaf(a2, a2, fmaf(a3, a3, ss1));
            }
            ss0 += __shfl_xor_sync(0xffffffffu, ss0, 1);
            ss0 += __shfl_xor_sync(0xffffffffu, ss0, 2);
            ss1 += __shfl_xor_sync(0xffffffffu, ss1, 1);
            ss1 += __shfl_xor_sync(0xffffffffu, ss1, 2);
            if ((lane & 3) == 0) {
                part[(size_t)m * 32 + slot]       = ss0;
                part[(size_t)(m + 8) * 32 + slot] = ss1;
            }
        }
    } else {
        // ---------------- phi: 2-stage, 3 passes, 4 tiles ----------------
        const int n0 = ((int)blockIdx.x - 16) * 128;
        const bool active = (n0 + wn) < LHc;       // skip pure-padding warp columns
        const __half* tp[4] = { Ah + (size_t)m0 * KKc, Al + (size_t)m0 * KKc,
                                Bh2 + (size_t)n0 * KKc, Bl2 + (size_t)n0 * KKc };

        auto load_stage4 = [&](int c, int st) {
            const uint32_t base = sb + st * STG4;
            #pragma unroll
            for (int i = 0; i < 16; i++) {
                const int idx = tid + i * 128;       // 0..2047
                const int t   = idx >> 9;
                const int rem = idx & 511;
                const int row = rem >> 2;
                const int ch  = rem & 3;
                cp_async16(base + t * TILE + row * RB + ch * 16,
                           tp[t] + (size_t)row * KKc + c * 32 + ch * 8);
            }
            CP_COMMIT();
        };

        load_stage4(0, 0);

        for (int c = 0; c < NCH; c++) {
            if (c + 1 < NCH) { load_stage4(c + 1, (c + 1) & 1); CP_WAIT1(); }
            else             { CP_WAIT0(); }
            __syncthreads();

            const uint32_t stb = sb + (c & 1) * STG4;
            if (active) {
                #pragma unroll
                for (int ks = 0; ks < 2; ks++) {
                    const uint32_t ko = ks * 32;
                    uint32_t ah[4][4], bh[4][4], xx[4][4];

                    #pragma unroll
                    for (int mt = 0; mt < 4; mt++)
                        LDSM4(ah[mt][0], ah[mt][1], ah[mt][2], ah[mt][3], stb + aOff[mt] + ko);
                    #pragma unroll
                    for (int nt2 = 0; nt2 < 4; nt2++)
                        LDSM4(bh[nt2][0], bh[nt2][1], bh[nt2][2], bh[nt2][3], stb + bOff[nt2] + ko);
                    #pragma unroll
                    for (int mt = 0; mt < 4; mt++)
                        #pragma unroll
                        for (int nt = 0; nt < 8; nt++) {
                            const uint32_t* bb = &bh[nt >> 1][(nt & 1) * 2];
                            MMA_F16(acc[mt][nt], ah[mt][0], ah[mt][1], ah[mt][2], ah[mt][3], bb[0], bb[1]);
                        }

                    #pragma unroll
                    for (int mt = 0; mt < 4; mt++)
                        LDSM4(xx[mt][0], xx[mt][1], xx[mt][2], xx[mt][3], stb + TILE + aOff[mt] + ko);
                    #pragma unroll
                    for (int mt = 0; mt < 4; mt++)
                        #pragma unroll
                        for (int nt = 0; nt < 8; nt++) {
                            const uint32_t* bb = &bh[nt >> 1][(nt & 1) * 2];
                            MMA_F16(acc[mt][nt], xx[mt][0], xx[mt][1], xx[mt][2], xx[mt][3], bb[0], bb[1]);
                        }

                    #pragma unroll
                    for (int nt2 = 0; nt2 < 4; nt2++)
                        LDSM4(xx[nt2][0], xx[nt2][1], xx[nt2][2], xx[nt2][3], stb + TILE + bOff[nt2] + ko);
                    #pragma unroll
                    for (int mt = 0; mt < 4; mt++)
                        #pragma unroll
                        for (int nt = 0; nt < 8; nt++) {
                            const uint32_t* bb = &xx[nt >> 1][(nt & 1) * 2];
                            MMA_F16(acc[mt][nt], ah[mt][0], ah[mt][1], ah[mt][2], ah[mt][3], bb[0], bb[1]);
                        }
                }
            }
            __syncthreads();
        }

        if (active) {
            #pragma unroll
            for (int mt = 0; mt < 4; mt++) {
                const int m = m0 + wm + mt * 16 + (lane >> 2);
                #pragma unroll
                for (int nt = 0; nt < 8; nt++) {
                    const int n = n0 + wn + nt * 8 + (lane & 3) * 2;
                    *(float2*)(C2 + (size_t)m * 256 + n)       = make_float2(acc[mt][nt][0], acc[mt][nt][1]);
                    *(float2*)(C2 + (size_t)(m + 8) * 256 + n) = make_float2(acc[mt][nt][2], acc[mt][nt][3]);
                }
            }
        }
    }
}

// ================= GEMM3: single-pass fp16 ==================
__global__ __launch_bounds__(128, 2)
void f16_gemm1(const __half* __restrict__ A, const __half* __restrict__ B,
               float* __restrict__ C)
{
    extern __shared__ char smem[];
    const uint32_t sb = smem_u32(smem);
    const int tid  = threadIdx.x;
    const int wid  = tid >> 5;
    const int lane = tid & 31;
    const int m0 = blockIdx.y * 128;
    const int n0 = blockIdx.x * 128;
    const int wm = (wid & 1) * 64;
    const int wn = (wid >> 1) * 64;

    const int g = lane >> 3, r = lane & 7;
    uint32_t aOff[4], bOff[4];
    #pragma unroll
    for (int mt = 0; mt < 4; mt++)
        aOff[mt] = (uint32_t)((wm + mt * 16 + (g & 1) * 8 + r) * RB + (g >> 1) * 16);
    #pragma unroll
    for (int nt2 = 0; nt2 < 4; nt2++)
        bOff[nt2] = (uint32_t)(TILE + (wn + nt2 * 16 + (g >> 1) * 8 + r) * RB + (g & 1) * 16);

    float acc[4][8][4];
    #pragma unroll
    for (int i = 0; i < 4; i++)
        #pragma unroll
        for (int j = 0; j < 8; j++)
            #pragma unroll
            for (int v = 0; v < 4; v++) acc[i][j][v] = 0.f;

    const __half* tp[2] = { A + (size_t)m0 * KKc, B + (size_t)n0 * KKc };

    auto load_stage = [&](int c, int st) {
        const uint32_t base = sb + st * STG2;
        #pragma unroll
        for (int t = 0; t < 2; t++) {
            const __half* src = tp[t] + c * 32;
            #pragma unroll
            for (int i = 0; i < 4; i++) {
                const int idx = tid + i * 128;
                const int row = idx >> 2;
                const int ch  = idx & 3;
                cp_async16(base + t * TILE + row * RB + ch * 16,
                           src + (size_t)row * KKc + ch * 8);
            }
        }
        CP_COMMIT();
    };

    load_stage(0, 0);
    load_stage(1, 1);

    for (int c = 0; c < NCH; c++) {
        if (c + 1 < NCH) CP_WAIT1(); else CP_WAIT0();
        __syncthreads();
        if (c + 2 < NCH) load_stage(c + 2, (c + 2) % 3);

        const uint32_t stb = sb + (c % 3) * STG2;
        #pragma unroll
        for (int ks = 0; ks < 2; ks++) {
            const uint32_t ko = ks * 32;
            uint32_t ah[4][4], bh[4][4];
            #pragma unroll
            for (int mt = 0; mt < 4; mt++)
                LDSM4(ah[mt][0], ah[mt][1], ah[mt][2], ah[mt][3], stb + aOff[mt] + ko);
            #pragma unroll
            for (int nt2 = 0; nt2 < 4; nt2++)
                LDSM4(bh[nt2][0], bh[nt2][1], bh[nt2][2], bh[nt2][3], stb + bOff[nt2] + ko);
            #pragma unroll
            for (int mt = 0; mt < 4; mt++)
                #pragma unroll
                for (int nt = 0; nt < 8; nt++) {
                    const uint32_t* bb = &bh[nt >> 1][(nt & 1) * 2];
                    MMA_F16(acc[mt][nt], ah[mt][0], ah[mt][1], ah[mt][2], ah[mt][3], bb[0], bb[1]);
                }
        }
    }

    #pragma unroll
    for (int mt = 0; mt < 4; mt++) {
        const int m = m0 + wm + mt * 16 + (lane >> 2);
        #pragma unroll
        for (int nt = 0; nt < 8; nt++) {
            const int n = n0 + wn + nt * 8 + (lane & 3) * 2;
            *(float2*)(C + (size_t)m * Dc + n)       = make_float2(acc[mt][nt][0], acc[mt][nt][1]);
            *(float2*)(C + (size_t)(m + 8) * Dc + n) = make_float2(acc[mt][nt][2], acc[mt][nt][3]);
        }
    }
}

// ---------------- fused operand conversions (one kernel) ----------------
__device__ __forceinline__ void split4(float4 v, uint2* H, uint2* L, int i) {
    __half h0 = __float2half_rn(v.x), h1 = __float2half_rn(v.y);
    __half h2 = __float2half_rn(v.z), h3 = __float2half_rn(v.w);
    __half l0 = __float2half_rn(v.x - __half2float(h0));
    __half l1 = __float2half_rn(v.y - __half2float(h1));
    __half l2 = __float2half_rn(v.z - __half2float(h2));
    __half l3 = __float2half_rn(v.w - __half2float(h3));
    __half2 ha = {h0, h1}, hb = {h2, h3}, la = {l0, l1}, lb = {l2, l3};
    H[i] = make_uint2(*(uint32_t*)&ha, *(uint32_t*)&hb);
    L[i] = make_uint2(*(uint32_t*)&la, *(uint32_t*)&lb);
}
__device__ __forceinline__ void cvt4(float4 v, uint2* H, int i) {
    __half2 a = __floats2half2_rn(v.x, v.y);
    __half2 b = __floats2half2_rn(v.z, v.w);
    H[i] = make_uint2(*(uint32_t*)&a, *(uint32_t*)&b);
}

#define N_X  (Mc * Dc / 4)
#define N_W  (Dc * Dc / 4)
#define N_L  (LHc * Dc / 4)
#define N_ALL (N_X + 2 * N_W + N_L)

__global__ void cvt_all(const float4* __restrict__ x, const float4* __restrict__ wt,
                        const float4* __restrict__ wo, const float4* __restrict__ wl,
                        uint2* __restrict__ xh, uint2* __restrict__ xl,
                        uint2* __restrict__ wth, uint2* __restrict__ woh,
                        uint2* __restrict__ wlh, uint2* __restrict__ wll)
{
    int i = blockIdx.x * blockDim.x + threadIdx.x;
    if (i < N_X) {
        split4(x[i], xh, xl, i);
    } else if (i < N_X + N_W) {
        int j = i - N_X;
        cvt4(wt[j], wth, j);
    } else if (i < N_X + 2 * N_W) {
        int j = i - N_X - N_W;
        cvt4(wo[j], woh, j);
    } else if (i < N_ALL) {
        int j = i - N_X - 2 * N_W;
        split4(wl[j], wlh, wll, j);
    }
}

// ------- fused: theta-scale finish + RMSNorm(phi) + sincos transpose -------
__global__ __launch_bounds__(192)
void phi_rms_sincos(const float* __restrict__ phi, const float* __restrict__ part,
                    float* __restrict__ tscale, float2* __restrict__ sc)
{
    const int row = blockIdx.x;            // b*4096 + t
    const int t   = row & (Tc - 1);
    const int b   = row >> 12;
    const int j   = threadIdx.x;           // 0..191

    // warp 0: finish theta rms scale from 32 slab partials
    if (j < 32) {
        float ss = part[(size_t)row * 32 + j];
        #pragma unroll
        for (int o = 16; o > 0; o >>= 1) ss += __shfl_xor_sync(0xffffffffu, ss, o);
        if (j == 0) tscale[row] = rsqrtf(ss / (float)Dc + EPSV);
    }

    const float v = phi[(size_t)row * 256 + j];
    float ss = v * v;
    #pragma unroll
    for (int o = 16; o > 0; o >>= 1) ss += __shfl_xor_sync(0xffffffffu, ss, o);
    __shared__ float red[6];
    const int warp = j >> 5, lane = j & 31;
    if (lane == 0) red[warp] = ss;
    __syncthreads();
    float tot = red[0] + red[1] + red[2] + red[3] + red[4] + red[5];
    const float rs = rsqrtf(tot / (float)LHc + EPSV);

    float s, c;
    sincosf(v * rs, &s, &c);
    const int l = j >> 4, h = j & 15;
    sc[((size_t)(b * Hc + h) * Lc + l) * Tc + t] = make_float2(c * INVSQRT2, s * INVSQRT2);
}

// ---------------- fused 12-level butterfly (fp16 in-place, level-pair fused) -
// Two levels per smem round-trip: theta_{l+2}[t] = w2.x*u + w2.y*v where
//   u = w1[t].x*cur + w1[t].y*th[t-s]          (this thread's level-(l+1) value)
//   v = w1[t-2s].x*th[t-2s] + w1[t-2s].y*th[t-3s]   (recomputed, bit-identical)
// Syncs per CTA: 23 -> 12; STS phases: 11 -> 5. Arithmetic order per element
// identical to the unfused version -> bit-identical output.
#define BSTR 12
__global__ __launch_bounds__(512, 1)
void butterfly_fused(__half* __restrict__ Th, const float* __restrict__ tscale,
                     const float2* __restrict__ sc)
{
    extern __shared__ float th[];   // [4096][BSTR]
    const int ds  = blockIdx.x;     // 0..15
    const int h   = blockIdx.y;     // 0..15
    const int b   = blockIdx.z;     // 0..1
    const int tid = threadIdx.x;
    const int cb  = h * 128 + ds * 8;
    const size_t rowbase = (size_t)b * Tc;

    float cur[8][8];

    #pragma unroll
    for (int k = 0; k < 8; k++) {
        const int t = tid + k * 512;
        const float scl = tscale[rowbase + t];
        uint4 raw = *(const uint4*)(Th + (rowbase + t) * Dc + cb);
        const __half2* hp = (const __half2*)&raw;
        #pragma unroll
        for (int p = 0; p < 4; p++) {
            float2 f = __half22float2(hp[p]);
            cur[k][p * 2]     = f.x * scl;
            cur[k][p * 2 + 1] = f.y * scl;
        }
        float* s = &th[t * BSTR];
        *(float4*)s       = make_float4(cur[k][0], cur[k][1], cur[k][2], cur[k][3]);
        *(float4*)(s + 4) = make_float4(cur[k][4], cur[k][5], cur[k][6], cur[k][7]);
    }
    __syncthreads();

    const float2* scb = sc + (size_t)(b * Hc + h) * Lc * Tc;
    for (int sl = 0; sl < Lc / 2; sl++) {
        const int s  = 1 << (2 * sl);       // step of level 2*sl
        const int l0 = 2 * sl;
        #pragma unroll
        for (int k = 0; k < 8; k++) {
            const int t = tid + k * 512;
            const float2 w1t = scb[l0 * Tc + t];
            const float2 w2t = scb[(l0 + 1) * Tc + t];
            const int t2 = t - 2 * s;
            const float2 w1p = scb[l0 * Tc + (t2 > 0 ? t2 : 0)];

            float4 A0 = make_float4(0.f, 0.f, 0.f, 0.f), A1 = A0;   // th[t-s]
            float4 B0 = A0, B1 = A0;                                // th[t-2s]
            float4 C0 = A0, C1 = A0;                                // th[t-3s]
            if (t >= s) {
                const float* ps = &th[(t - s) * BSTR];
                A0 = *(const float4*)ps; A1 = *(const float4*)(ps + 4);
            }
            if (t >= 2 * s) {
                const float* ps = &th[t2 * BSTR];
                B0 = *(const float4*)ps; B1 = *(const float4*)(ps + 4);
            }
            if (t >= 3 * s) {
                const float* ps = &th[(t - 3 * s) * BSTR];
                C0 = *(const float4*)ps; C1 = *(const float4*)(ps + 4);
            }

            const float* Af = (const float*)&A0;   // A0..A1 contiguous? not guaranteed; index explicitly
            // unrolled per element to keep exact fma ordering
            {
                float u, v;
                u = fmaf(w1t.x, cur[k][0], w1t.y * A0.x); v = fmaf(w1p.x, B0.x, w1p.y * C0.x);
                cur[k][0] = fmaf(w2t.x, u, w2t.y * v);
                u = fmaf(w1t.x, cur[k][1], w1t.y * A0.y); v = fmaf(w1p.x, B0.y, w1p.y * C0.y);
                cur[k][1] = fmaf(w2t.x, u, w2t.y * v);
                u = fmaf(w1t.x, cur[k][2], w1t.y * A0.z); v = fmaf(w1p.x, B0.z, w1p.y * C0.z);
                cur[k][2] = fmaf(w2t.x, u, w2t.y * v);
                u = fmaf(w1t.x, cur[k][3], w1t.y * A0.w); v = fmaf(w1p.x, B0.w, w1p.y * C0.w);
                cur[k][3] = fmaf(w2t.x, u, w2t.y * v);
                u = fmaf(w1t.x, cur[k][4], w1t.y * A1.x); v = fmaf(w1p.x, B1.x, w1p.y * C1.x);
                cur[k][4] = fmaf(w2t.x, u, w2t.y * v);
                u = fmaf(w1t.x, cur[k][5], w1t.y * A1.y); v = fmaf(w1p.x, B1.y, w1p.y * C1.y);
                cur[k][5] = fmaf(w2t.x, u, w2t.y * v);
                u = fmaf(w1t.x, cur[k][6], w1t.y * A1.z); v = fmaf(w1p.x, B1.z, w1p.y * C1.z);
                cur[k][6] = fmaf(w2t.x, u, w2t.y * v);
                u = fmaf(w1t.x, cur[k][7], w1t.y * A1.w); v = fmaf(w1p.x, B1.w, w1p.y * C1.w);
                cur[k][7] = fmaf(w2t.x, u, w2t.y * v);
            }
            (void)Af;
        }
        __syncthreads();                 // all reads of old super-level done
        if (sl < Lc / 2 - 1) {
            #pragma unroll
            for (int k = 0; k < 8; k++) {
                float* s2 = &th[(tid + k * 512) * BSTR];
                *(float4*)s2       = make_float4(cur[k][0], cur[k][1], cur[k][2], cur[k][3]);
                *(float4*)(s2 + 4) = make_float4(cur[k][4], cur[k][5], cur[k][6], cur[k][7]);
            }
            __syncthreads();             // new super-level visible
        }
    }

    #pragma unroll
    for (int k = 0; k < 8; k++) {
        const int t = tid + k * 512;
        __half2 h0 = __floats2half2_rn(cur[k][0], cur[k][1]);
        __half2 h1 = __floats2half2_rn(cur[k][2], cur[k][3]);
        __half2 h2 = __floats2half2_rn(cur[k][4], cur[k][5]);
        __half2 h3 = __floats2half2_rn(cur[k][6], cur[k][7]);
        uint4 o;
        o.x = *(uint32_t*)&h0; o.y = *(uint32_t*)&h1;
        o.z = *(uint32_t*)&h2; o.w = *(uint32_t*)&h3;
        *(uint4*)(Th + (rowbase + t) * Dc + cb) = o;
    }
}

// ---------------- launcher ----------------
extern "C" void kernel_launch(void* const* d_in, const int* in_sizes, int n_in,
                              void* d_out, int out_size)
{
    const float* x     = (const float*)d_in[0];
    const float* W_tok = (const float*)d_in[1];
    const float* W_lvl = (const float*)d_in[2];
    const float* W_out = (const float*)d_in[3];
    float* out = (float*)d_out;

    __half *xh, *xl, *wth, *woh, *wlh, *wll, *thh;
    float *phi, *tscale, *part; float2* sc;
    cudaGetSymbolAddress((void**)&xh,  g_xh);   cudaGetSymbolAddress((void**)&xl,  g_xl);
    cudaGetSymbolAddress((void**)&wth, g_wth);  cudaGetSymbolAddress((void**)&woh, g_woh);
    cudaGetSymbolAddress((void**)&wlh, g_wlh);  cudaGetSymbolAddress((void**)&wll, g_wll);
    cudaGetSymbolAddress((void**)&thh, g_thh);
    cudaGetSymbolAddress((void**)&part,   g_part);
    cudaGetSymbolAddress((void**)&phi,    g_phi);
    cudaGetSymbolAddress((void**)&tscale, g_tscale);
    cudaGetSymbolAddress((void**)&sc,     g_sc);

    const int SMEM_MAIN  = 2 * STG4;            // 81920 (covers 3*STG2=61440 too)
    const int SMEM_G3    = 3 * STG2;            // 61440
    const int SMEM_BFLY  = 4096 * BSTR * 4;     // 196608
    cudaFuncSetAttribute(f16_gemm_main, cudaFuncAttributeMaxDynamicSharedMemorySize, SMEM_MAIN);
    cudaFuncSetAttribute(f16_gemm1, cudaFuncAttributeMaxDynamicSharedMemorySize, SMEM_G3);
    cudaFuncSetAttribute(butterfly_fused, cudaFuncAttributeMaxDynamicSharedMemorySize, SMEM_BFLY);

    // 1) all operand conversions in one kernel
    cvt_all<<<(N_ALL + 255) / 256, 256>>>((const float4*)x, (const float4*)W_tok,
                                          (const float4*)W_out, (const float4*)W_lvl,
                                          (uint2*)xh, (uint2*)xl, (uint2*)wth,
                                          (uint2*)woh, (uint2*)wlh, (uint2*)wll);

    // 2) merged GEMM: theta (fp16 out + ssq partials) + phi
    f16_gemm_main<<<dim3(18, Mc / 128), 128, SMEM_MAIN>>>(xh, xl, wth, thh, part,
                                                          wlh, wll, phi);

    // 3) fused theta-scale finish + RMSNorm(phi) + sincos
    phi_rms_sincos<<<Mc, 192>>>(phi, part, tscale, sc);

    // 4) fused butterfly (level-pair fused, fp16 in-place)
    butterfly_fused<<<dim3(16, Hc, 2), 512, SMEM_BFLY>>>(thh, tscale, sc);

    // 5) y = theta @ W_out^T  (single-pass fp16)
    f16_gemm1<<<dim3(16, Mc / 128), 128, SMEM_G3>>>(thh, woh, out);
}